// round 5
// baseline (speedup 1.0000x reference)
#include <cuda_runtime.h>

// moving_image [1,1,192,192,192] f32, vector_field [1,3,192,192,192] f32,
// fixed_image [1,1,192,192,192] f32, fixed_image_mask (uint8/int32/float32, runtime-detected).
// Output scalar f32 = sum((warp(mov,vf)-fixed)^2 * mask) / max(sum(mask),1).

#define DD 192
#define HH 192
#define WW 192
#define NVOX (DD * HH * WW)

#define THREADS 256                       // 8 warps; 1 warp = 1 row
#define ROWS_PER_BLK 8
#define NBLK ((DD * HH) / ROWS_PER_BLK)   // 4608
#define XITER (WW / 32)                   // 6 voxels per lane, x = lane + 32*j

__device__ float g_part_sq[NBLK];
__device__ float g_part_m[NBLK];
__device__ unsigned int g_done = 0;       // reset by last block each run -> replay-safe

__device__ __forceinline__ float sample_zero_pad(const float* __restrict__ mov,
                                                 int iz, int iy, int ix) {
    if ((unsigned)iz >= DD || (unsigned)iy >= HH || (unsigned)ix >= WW) return 0.0f;
    return __ldg(mov + (iz * HH + iy) * WW + ix);
}

// x-lerp of row[x0], row[x0+1] via one aligned float4 (single 128B line) plus a
// predicated scalar fixup when x0%4==3. Valid for 0 <= x0 <= WW-2.
__device__ __forceinline__ float row_xlerp(const float* __restrict__ row,
                                           int w, int o, float wx) {
    float4 v = __ldg((const float4*)(row + w));
    float a = (o < 2) ? (o ? v.y : v.x) : ((o == 2) ? v.z : v.w);
    float b;
    if (o == 3) {
        b = __ldg(row + w + 4);
    } else {
        b = (o < 2) ? (o ? v.z : v.y) : v.w;
    }
    return fmaf(wx, b - a, a);
}

__device__ __forceinline__ float trilerp(const float* __restrict__ mov,
                                         float zz, float yy, float xx) {
    int z0 = __float2int_rd(zz);
    int y0 = __float2int_rd(yy);
    int x0 = __float2int_rd(xx);
    float wz = zz - (float)z0;
    float wy = yy - (float)y0;
    float wx = xx - (float)x0;

    if ((unsigned)z0 <= DD - 2 && (unsigned)y0 <= HH - 2 && (unsigned)x0 <= WW - 2) {
        const float* r00 = mov + ((z0 * HH + y0) * WW);
        const float* r01 = r00 + WW;
        const float* r10 = r00 + HH * WW;
        const float* r11 = r10 + WW;
        int w = x0 & ~3;
        int o = x0 & 3;
        float l00 = row_xlerp(r00, w, o, wx);
        float l01 = row_xlerp(r01, w, o, wx);
        float l10 = row_xlerp(r10, w, o, wx);
        float l11 = row_xlerp(r11, w, o, wx);
        float lz0 = fmaf(wy, l01 - l00, l00);
        float lz1 = fmaf(wy, l11 - l10, l10);
        return fmaf(wz, lz1 - lz0, lz0);
    } else {
        float wz0 = 1.0f - wz, wy0 = 1.0f - wy, wx0 = 1.0f - wx;
        int z1 = z0 + 1, y1 = y0 + 1, x1 = x0 + 1;
        float c000 = sample_zero_pad(mov, z0, y0, x0);
        float c001 = sample_zero_pad(mov, z0, y0, x1);
        float c010 = sample_zero_pad(mov, z0, y1, x0);
        float c011 = sample_zero_pad(mov, z0, y1, x1);
        float c100 = sample_zero_pad(mov, z1, y0, x0);
        float c101 = sample_zero_pad(mov, z1, y0, x1);
        float c110 = sample_zero_pad(mov, z1, y1, x0);
        float c111 = sample_zero_pad(mov, z1, y1, x1);
        return wz0 * (wy0 * (wx0 * c000 + wx * c001) +
                      wy  * (wx0 * c010 + wx * c011)) +
               wz  * (wy0 * (wx0 * c100 + wx * c101) +
                      wy  * (wx0 * c110 + wx * c111));
    }
}

__global__ __launch_bounds__(THREADS) void warp_mse_kernel(
    const float* __restrict__ mov,
    const float* __restrict__ vf,
    const float* __restrict__ fix,
    const void* __restrict__ mask_raw,
    float* __restrict__ out) {

    __shared__ int sh_mode;
    __shared__ bool sh_last;

    const int tid = threadIdx.x;
    const int lane = tid & 31;
    const int wid = tid >> 5;

    // Per-block mask encoding detection from the first 256 bytes (L2/L1-resident).
    //  - float32 0/1: byte 0x3f at pos%4==3 or 0x80 at pos%4==2 -> mode 2
    //  - int32 0/1: all bytes at pos%4!=0 zero -> mode 1
    //  - uint8 0/1: nonzero byte at pos%4!=0 (P[miss] ~ 2^-192) -> mode 0
    if (wid == 0) {
        const unsigned char* mb = (const unsigned char*)mask_raw;
        int f32 = 0, mis = 0;
#pragma unroll
        for (int k = 0; k < 8; k++) {
            int pos = lane * 8 + k;
            unsigned char b = __ldg(mb + pos);
            int off = pos & 3;
            if (off == 3 && b == 0x3f) f32 = 1;
            if (off == 2 && b == 0x80) f32 = 1;
            if (off != 0 && b != 0) mis = 1;
        }
        unsigned f32b = __ballot_sync(0xffffffffu, f32);
        unsigned misb = __ballot_sync(0xffffffffu, mis);
        if (lane == 0) sh_mode = f32b ? 2 : (misb ? 0 : 1);
    }
    __syncthreads();
    const int mask_mode = sh_mode;

    const int row = blockIdx.x * ROWS_PER_BLK + wid;
    const int y = row % HH;
    const int z = row / HH;
    const int rowbase = row * WW;
    const float zf = (float)z;
    const float yf = (float)y;

    float s_sq = 0.0f;
    float s_m = 0.0f;

#pragma unroll
    for (int j = 0; j < XITER; j++) {
        const int x = lane + 32 * j;
        const int idx = rowbase + x;

        float dz = __ldg(vf + idx);
        float dy = __ldg(vf + idx + NVOX);
        float dx = __ldg(vf + idx + 2 * NVOX);
        float fv = __ldg(fix + idx);

        float m;
        if (mask_mode == 1) {
            m = (float)__ldg((const int*)mask_raw + idx);
        } else if (mask_mode == 2) {
            m = __ldg((const float*)mask_raw + idx);
        } else {
            m = (float)__ldg((const unsigned char*)mask_raw + idx);
        }

        float warped = trilerp(mov, zf + dz, yf + dy, (float)x + dx);
        float d = warped - fv;
        s_sq = fmaf(d * d, m, s_sq);
        s_m += m;
    }

    // Deterministic block tree reduction.
    __shared__ float sh_sq[THREADS];
    __shared__ float sh_m[THREADS];
    sh_sq[tid] = s_sq;
    sh_m[tid] = s_m;
    __syncthreads();
    for (int off = THREADS / 2; off > 0; off >>= 1) {
        if (tid < off) {
            sh_sq[tid] += sh_sq[tid + off];
            sh_m[tid] += sh_m[tid + off];
        }
        __syncthreads();
    }
    if (tid == 0) {
        g_part_sq[blockIdx.x] = sh_sq[0];
        g_part_m[blockIdx.x] = sh_m[0];
        __threadfence();
        unsigned int t = atomicAdd(&g_done, 1u);
        sh_last = (t == (unsigned)(NBLK - 1));
    }
    __syncthreads();

    // Last block reduces all partials (fixed index order -> deterministic).
    if (sh_last) {
        float t_sq = 0.0f, t_m = 0.0f;
        for (int i = tid; i < NBLK; i += THREADS) {
            t_sq += g_part_sq[i];
            t_m += g_part_m[i];
        }
        sh_sq[tid] = t_sq;
        sh_m[tid] = t_m;
        __syncthreads();
        for (int off = THREADS / 2; off > 0; off >>= 1) {
            if (tid < off) {
                sh_sq[tid] += sh_sq[tid + off];
                sh_m[tid] += sh_m[tid + off];
            }
            __syncthreads();
        }
        if (tid == 0) {
            out[0] = sh_sq[0] / fmaxf(sh_m[0], 1.0f);
            g_done = 0;  // reset for next graph replay
        }
    }
}

extern "C" void kernel_launch(void* const* d_in, const int* in_sizes, int n_in,
                              void* d_out, int out_size) {
    const float* mov = (const float*)d_in[0];
    const float* vf = (const float*)d_in[1];
    const float* fix = (const float*)d_in[2];
    const void* mask = d_in[3];
    float* out = (float*)d_out;

    warp_mse_kernel<<<NBLK, THREADS>>>(mov, vf, fix, mask, out);
}

// round 6
// speedup vs baseline: 1.0532x; 1.0532x over previous
#include <cuda_runtime.h>

// moving_image [1,1,192,192,192] f32, vector_field [1,3,192,192,192] f32,
// fixed_image [1,1,192,192,192] f32, fixed_image_mask (uint8/int32/float32, runtime-detected).
// Output scalar f32 = sum((warp(mov,vf)-fixed)^2 * mask) / max(sum(mask),1).

#define DD 192
#define HH 192
#define WW 192
#define NVOX (DD * HH * WW)

#define THREADS 256                       // 8 warps; 1 warp = 1 row
#define ROWS_PER_BLK 8
#define NBLK ((DD * HH) / ROWS_PER_BLK)   // 4608
#define XITER (WW / 32)                   // 6 voxels per lane, x = lane + 32*j

__device__ float g_part_sq[NBLK];
__device__ float g_part_m[NBLK];
__device__ unsigned int g_done = 0;       // reset by last block each run -> replay-safe

// Branchless trilinear sample with zero padding: always 8 in-bounds gathers at
// clamped indices, corner values multiplied by validity.
__device__ __forceinline__ float trilerp(const float* __restrict__ mov,
                                         float zz, float yy, float xx) {
    int z0 = __float2int_rd(zz);
    int y0 = __float2int_rd(yy);
    int x0 = __float2int_rd(xx);
    float wz = zz - (float)z0;
    float wy = yy - (float)y0;
    float wx = xx - (float)x0;
    int z1 = z0 + 1, y1 = y0 + 1, x1 = x0 + 1;

    float vz0 = ((unsigned)z0 < DD) ? 1.0f : 0.0f;
    float vz1 = ((unsigned)z1 < DD) ? 1.0f : 0.0f;
    float vy0 = ((unsigned)y0 < HH) ? 1.0f : 0.0f;
    float vy1 = ((unsigned)y1 < HH) ? 1.0f : 0.0f;
    float vx0 = ((unsigned)x0 < WW) ? 1.0f : 0.0f;
    float vx1 = ((unsigned)x1 < WW) ? 1.0f : 0.0f;

    int zc0 = min(max(z0, 0), DD - 1), zc1 = min(max(z1, 0), DD - 1);
    int yc0 = min(max(y0, 0), HH - 1), yc1 = min(max(y1, 0), HH - 1);
    int xc0 = min(max(x0, 0), WW - 1), xc1 = min(max(x1, 0), WW - 1);

    const float* p00 = mov + (zc0 * HH + yc0) * WW;  // z0,y0
    const float* p01 = mov + (zc0 * HH + yc1) * WW;  // z0,y1
    const float* p10 = mov + (zc1 * HH + yc0) * WW;  // z1,y0
    const float* p11 = mov + (zc1 * HH + yc1) * WW;  // z1,y1

    float c000 = __ldg(p00 + xc0) * vx0;
    float c001 = __ldg(p00 + xc1) * vx1;
    float c010 = __ldg(p01 + xc0) * vx0;
    float c011 = __ldg(p01 + xc1) * vx1;
    float c100 = __ldg(p10 + xc0) * vx0;
    float c101 = __ldg(p10 + xc1) * vx1;
    float c110 = __ldg(p11 + xc0) * vx0;
    float c111 = __ldg(p11 + xc1) * vx1;

    // x-lerp, then fold y/z validity into the y/z combine.
    float l00 = fmaf(wx, c001 - c000, c000) * vy0;
    float l01 = fmaf(wx, c011 - c010, c010) * vy1;
    float l10 = fmaf(wx, c101 - c100, c100) * vy0;
    float l11 = fmaf(wx, c111 - c110, c110) * vy1;

    float lz0 = (fmaf(wy, l01, 0.0f) + (1.0f - wy) * l00) * vz0;
    float lz1 = (fmaf(wy, l11, 0.0f) + (1.0f - wy) * l10) * vz1;
    return fmaf(wz, lz1, (1.0f - wz) * lz0);
}

__global__ __launch_bounds__(THREADS, 4) void warp_mse_kernel(
    const float* __restrict__ mov,
    const float* __restrict__ vf,
    const float* __restrict__ fix,
    const void* __restrict__ mask_raw,
    float* __restrict__ out) {

    __shared__ int sh_mode;
    __shared__ bool sh_last;

    const int tid = threadIdx.x;
    const int lane = tid & 31;
    const int wid = tid >> 5;

    // Per-block mask encoding detection from the first 256 bytes (L1/L2-resident).
    if (wid == 0) {
        const unsigned char* mb = (const unsigned char*)mask_raw;
        int f32 = 0, mis = 0;
#pragma unroll
        for (int k = 0; k < 8; k++) {
            int pos = lane * 8 + k;
            unsigned char b = __ldg(mb + pos);
            int off = pos & 3;
            if (off == 3 && b == 0x3f) f32 = 1;
            if (off == 2 && b == 0x80) f32 = 1;
            if (off != 0 && b != 0) mis = 1;
        }
        unsigned f32b = __ballot_sync(0xffffffffu, f32);
        unsigned misb = __ballot_sync(0xffffffffu, mis);
        if (lane == 0) sh_mode = f32b ? 2 : (misb ? 0 : 1);
    }
    __syncthreads();
    const int mask_mode = sh_mode;

    const int row = blockIdx.x * ROWS_PER_BLK + wid;
    const int y = row % HH;
    const int z = row / HH;
    const int rowbase = row * WW;
    const float zf = (float)z;
    const float yf = (float)y;

    // Hoisted streaming loads for all XITER voxels (coalesced).
    float dzv[XITER], dyv[XITER], dxv[XITER], fv[XITER], mv[XITER];
#pragma unroll
    for (int j = 0; j < XITER; j++) {
        const int idx = rowbase + lane + 32 * j;
        dzv[j] = __ldg(vf + idx);
        dyv[j] = __ldg(vf + idx + NVOX);
        dxv[j] = __ldg(vf + idx + 2 * NVOX);
        fv[j] = __ldg(fix + idx);
    }
    if (mask_mode == 1) {
#pragma unroll
        for (int j = 0; j < XITER; j++)
            mv[j] = (float)__ldg((const int*)mask_raw + rowbase + lane + 32 * j);
    } else if (mask_mode == 2) {
#pragma unroll
        for (int j = 0; j < XITER; j++)
            mv[j] = __ldg((const float*)mask_raw + rowbase + lane + 32 * j);
    } else {
#pragma unroll
        for (int j = 0; j < XITER; j++)
            mv[j] = (float)__ldg((const unsigned char*)mask_raw + rowbase + lane + 32 * j);
    }

    float s_sq = 0.0f;
    float s_m = 0.0f;

#pragma unroll
    for (int j = 0; j < XITER; j++) {
        const int x = lane + 32 * j;
        float warped = trilerp(mov, zf + dzv[j], yf + dyv[j], (float)x + dxv[j]);
        float d = warped - fv[j];
        s_sq = fmaf(d * d, mv[j], s_sq);
        s_m += mv[j];
    }

    // Deterministic block tree reduction.
    __shared__ float sh_sq[THREADS];
    __shared__ float sh_m[THREADS];
    sh_sq[tid] = s_sq;
    sh_m[tid] = s_m;
    __syncthreads();
    for (int off = THREADS / 2; off > 0; off >>= 1) {
        if (tid < off) {
            sh_sq[tid] += sh_sq[tid + off];
            sh_m[tid] += sh_m[tid + off];
        }
        __syncthreads();
    }
    if (tid == 0) {
        g_part_sq[blockIdx.x] = sh_sq[0];
        g_part_m[blockIdx.x] = sh_m[0];
        __threadfence();
        unsigned int t = atomicAdd(&g_done, 1u);
        sh_last = (t == (unsigned)(NBLK - 1));
    }
    __syncthreads();

    // Last block reduces all partials (fixed index order -> deterministic).
    if (sh_last) {
        float t_sq = 0.0f, t_m = 0.0f;
        for (int i = tid; i < NBLK; i += THREADS) {
            t_sq += g_part_sq[i];
            t_m += g_part_m[i];
        }
        sh_sq[tid] = t_sq;
        sh_m[tid] = t_m;
        __syncthreads();
        for (int off = THREADS / 2; off > 0; off >>= 1) {
            if (tid < off) {
                sh_sq[tid] += sh_sq[tid + off];
                sh_m[tid] += sh_m[tid + off];
            }
            __syncthreads();
        }
        if (tid == 0) {
            out[0] = sh_sq[0] / fmaxf(sh_m[0], 1.0f);
            g_done = 0;  // reset for next graph replay
        }
    }
}

extern "C" void kernel_launch(void* const* d_in, const int* in_sizes, int n_in,
                              void* d_out, int out_size) {
    const float* mov = (const float*)d_in[0];
    const float* vf = (const float*)d_in[1];
    const float* fix = (const float*)d_in[2];
    const void* mask = d_in[3];
    float* out = (float*)d_out;

    warp_mse_kernel<<<NBLK, THREADS>>>(mov, vf, fix, mask, out);
}

// round 7
// speedup vs baseline: 1.1809x; 1.1213x over previous
#include <cuda_runtime.h>

// moving_image [1,1,192,192,192] f32, vector_field [1,3,192,192,192] f32,
// fixed_image [1,1,192,192,192] f32, fixed_image_mask (uint8/int32/float32, runtime-detected).
// Output scalar f32 = sum((warp(mov,vf)-fixed)^2 * mask) / max(sum(mask),1).

#define DD 192
#define HH 192
#define WW 192
#define NVOX (DD * HH * WW)

#define THREADS 256                       // 8 warps; 1 warp = 1 row
#define ROWS_PER_BLK 8
#define NBLK ((DD * HH) / ROWS_PER_BLK)   // 4608
#define XITER (WW / 32)                   // 6 voxels per lane, x = lane + 32*j

__device__ float g_part_sq[NBLK];
__device__ float g_part_m[NBLK];
__device__ unsigned int g_done = 0;       // reset by last block each run -> replay-safe

__device__ __forceinline__ float sample_zero_pad(const float* __restrict__ mov,
                                                 int iz, int iy, int ix) {
    if ((unsigned)iz >= DD || (unsigned)iy >= HH || (unsigned)ix >= WW) return 0.0f;
    return __ldg(mov + (iz * HH + iy) * WW + ix);
}

// Fast path: all 8 corners in-bounds, no predication.
__device__ __forceinline__ float trilerp_fast(const float* __restrict__ mov,
                                              int z0, int y0, int x0,
                                              float wz, float wy, float wx) {
    const float* p = mov + ((z0 * HH + y0) * WW + x0);
    float c000 = __ldg(p);
    float c001 = __ldg(p + 1);
    float c010 = __ldg(p + WW);
    float c011 = __ldg(p + WW + 1);
    const float* q = p + HH * WW;
    float c100 = __ldg(q);
    float c101 = __ldg(q + 1);
    float c110 = __ldg(q + WW);
    float c111 = __ldg(q + WW + 1);
    float l00 = fmaf(wx, c001 - c000, c000);
    float l01 = fmaf(wx, c011 - c010, c010);
    float l10 = fmaf(wx, c101 - c100, c100);
    float l11 = fmaf(wx, c111 - c110, c110);
    float lz0 = fmaf(wy, l01 - l00, l00);
    float lz1 = fmaf(wy, l11 - l10, l10);
    return fmaf(wz, lz1 - lz0, lz0);
}

__device__ __forceinline__ float trilerp_slow(const float* __restrict__ mov,
                                              int z0, int y0, int x0,
                                              float wz, float wy, float wx) {
    float wz0 = 1.0f - wz, wy0 = 1.0f - wy, wx0 = 1.0f - wx;
    int z1 = z0 + 1, y1 = y0 + 1, x1 = x0 + 1;
    float c000 = sample_zero_pad(mov, z0, y0, x0);
    float c001 = sample_zero_pad(mov, z0, y0, x1);
    float c010 = sample_zero_pad(mov, z0, y1, x0);
    float c011 = sample_zero_pad(mov, z0, y1, x1);
    float c100 = sample_zero_pad(mov, z1, y0, x0);
    float c101 = sample_zero_pad(mov, z1, y0, x1);
    float c110 = sample_zero_pad(mov, z1, y1, x0);
    float c111 = sample_zero_pad(mov, z1, y1, x1);
    return wz0 * (wy0 * (wx0 * c000 + wx * c001) +
                  wy  * (wx0 * c010 + wx * c011)) +
           wz  * (wy0 * (wx0 * c100 + wx * c101) +
                  wy  * (wx0 * c110 + wx * c111));
}

__device__ __forceinline__ float trilerp(const float* __restrict__ mov,
                                         float zz, float yy, float xx) {
    int z0 = __float2int_rd(zz);
    int y0 = __float2int_rd(yy);
    int x0 = __float2int_rd(xx);
    float wz = zz - (float)z0;
    float wy = yy - (float)y0;
    float wx = xx - (float)x0;

    bool interior = ((unsigned)z0 <= DD - 2) & ((unsigned)y0 <= HH - 2) &
                    ((unsigned)x0 <= WW - 2);
    // Warp-uniform branch: fully interior warps take the unpredicated fast path.
    if (__all_sync(0xffffffffu, interior)) {
        return trilerp_fast(mov, z0, y0, x0, wz, wy, wx);
    } else {
        return trilerp_slow(mov, z0, y0, x0, wz, wy, wx);
    }
}

__global__ __launch_bounds__(THREADS) void warp_mse_kernel(
    const float* __restrict__ mov,
    const float* __restrict__ vf,
    const float* __restrict__ fix,
    const void* __restrict__ mask_raw,
    float* __restrict__ out) {

    __shared__ int sh_mode;
    __shared__ bool sh_last;

    const int tid = threadIdx.x;
    const int lane = tid & 31;
    const int wid = tid >> 5;

    // Per-block mask encoding detection from the first 256 bytes (L1/L2-resident).
    if (wid == 0) {
        const unsigned char* mb = (const unsigned char*)mask_raw;
        int f32 = 0, mis = 0;
#pragma unroll
        for (int k = 0; k < 8; k++) {
            int pos = lane * 8 + k;
            unsigned char b = __ldg(mb + pos);
            int off = pos & 3;
            if (off == 3 && b == 0x3f) f32 = 1;
            if (off == 2 && b == 0x80) f32 = 1;
            if (off != 0 && b != 0) mis = 1;
        }
        unsigned f32b = __ballot_sync(0xffffffffu, f32);
        unsigned misb = __ballot_sync(0xffffffffu, mis);
        if (lane == 0) sh_mode = f32b ? 2 : (misb ? 0 : 1);
    }
    __syncthreads();
    const int mask_mode = sh_mode;

    const int row = blockIdx.x * ROWS_PER_BLK + wid;
    const int y = row % HH;
    const int z = row / HH;
    const int rowbase = row * WW;
    const float zf = (float)z;
    const float yf = (float)y;

    float s_sq = 0.0f;
    float s_m = 0.0f;

    // Pairwise software pipeline: stream 2 iterations, then 2 independent trilerps.
#pragma unroll
    for (int jj = 0; jj < XITER; jj += 2) {
        const int xA = lane + 32 * jj;
        const int xB = xA + 32;
        const int iA = rowbase + xA;
        const int iB = rowbase + xB;

        float dzA = __ldg(vf + iA);
        float dzB = __ldg(vf + iB);
        float dyA = __ldg(vf + iA + NVOX);
        float dyB = __ldg(vf + iB + NVOX);
        float dxA = __ldg(vf + iA + 2 * NVOX);
        float dxB = __ldg(vf + iB + 2 * NVOX);
        float fA = __ldg(fix + iA);
        float fB = __ldg(fix + iB);

        float mA, mB;
        if (mask_mode == 1) {
            mA = (float)__ldg((const int*)mask_raw + iA);
            mB = (float)__ldg((const int*)mask_raw + iB);
        } else if (mask_mode == 2) {
            mA = __ldg((const float*)mask_raw + iA);
            mB = __ldg((const float*)mask_raw + iB);
        } else {
            mA = (float)__ldg((const unsigned char*)mask_raw + iA);
            mB = (float)__ldg((const unsigned char*)mask_raw + iB);
        }

        float wA = trilerp(mov, zf + dzA, yf + dyA, (float)xA + dxA);
        float wB = trilerp(mov, zf + dzB, yf + dyB, (float)xB + dxB);

        float dA = wA - fA;
        float dB = wB - fB;
        s_sq = fmaf(dA * dA, mA, s_sq);
        s_sq = fmaf(dB * dB, mB, s_sq);
        s_m += mA + mB;
    }

    // Deterministic block tree reduction.
    __shared__ float sh_sq[THREADS];
    __shared__ float sh_m[THREADS];
    sh_sq[tid] = s_sq;
    sh_m[tid] = s_m;
    __syncthreads();
    for (int off = THREADS / 2; off > 0; off >>= 1) {
        if (tid < off) {
            sh_sq[tid] += sh_sq[tid + off];
            sh_m[tid] += sh_m[tid + off];
        }
        __syncthreads();
    }
    if (tid == 0) {
        g_part_sq[blockIdx.x] = sh_sq[0];
        g_part_m[blockIdx.x] = sh_m[0];
        __threadfence();
        unsigned int t = atomicAdd(&g_done, 1u);
        sh_last = (t == (unsigned)(NBLK - 1));
    }
    __syncthreads();

    // Last block reduces all partials (fixed index order -> deterministic).
    if (sh_last) {
        float t_sq = 0.0f, t_m = 0.0f;
        for (int i = tid; i < NBLK; i += THREADS) {
            t_sq += g_part_sq[i];
            t_m += g_part_m[i];
        }
        sh_sq[tid] = t_sq;
        sh_m[tid] = t_m;
        __syncthreads();
        for (int off = THREADS / 2; off > 0; off >>= 1) {
            if (tid < off) {
                sh_sq[tid] += sh_sq[tid + off];
                sh_m[tid] += sh_m[tid + off];
            }
            __syncthreads();
        }
        if (tid == 0) {
            out[0] = sh_sq[0] / fmaxf(sh_m[0], 1.0f);
            g_done = 0;  // reset for next graph replay
        }
    }
}

extern "C" void kernel_launch(void* const* d_in, const int* in_sizes, int n_in,
                              void* d_out, int out_size) {
    const float* mov = (const float*)d_in[0];
    const float* vf = (const float*)d_in[1];
    const float* fix = (const float*)d_in[2];
    const void* mask = d_in[3];
    float* out = (float*)d_out;

    warp_mse_kernel<<<NBLK, THREADS>>>(mov, vf, fix, mask, out);
}